// round 2
// baseline (speedup 1.0000x reference)
#include <cuda_runtime.h>
#include <math.h>

#define BQ    32
#define CIN   128
#define LIN   1024
#define NE    4
#define COUT  128
#define KW    64
#define LOUT  961          // 1024 - 64 + 1
#define NTILE 64
#define NTILES 16          // ceil(961/64)

// ---------------- scratch (device globals: no allocation allowed) ----------
__device__ float g_gatex[BQ * CIN];
__device__ int   g_sel [BQ * 2];
__device__ float g_selw[BQ * 2];

// ---------------- kernel 1: gate_x = mean over L --------------------------
__global__ void k_gatex(const float* __restrict__ x) {
    int b = blockIdx.x;
    int c = threadIdx.x;
    const float4* xp = (const float4*)(x + ((size_t)b * CIN + c) * LIN);
    float s = 0.f;
#pragma unroll 8
    for (int i = 0; i < LIN / 4; ++i) {
        float4 v = xp[i];
        s += (v.x + v.y) + (v.z + v.w);
    }
    g_gatex[b * CIN + c] = s * (1.0f / (float)LIN);
}

// ---------------- kernel 2: gating, top-k, loss ---------------------------
__device__ __forceinline__ float cv_sq4(const float* w) {
    float mn = 0.25f * (w[0] + w[1] + w[2] + w[3]);
    float s = 0.f;
#pragma unroll
    for (int e = 0; e < 4; ++e) { float d = w[e] - mn; s += d * d; }
    s *= (1.0f / 3.0f);                    // ddof = 1
    return s / (mn * mn + 1e-10f);
}

__global__ void k_gate(const float* __restrict__ noise,
                       const float* __restrict__ w_gate,
                       const float* __restrict__ w_noise,
                       float* __restrict__ out, int loss_idx)
{
    int b = threadIdx.x;                   // 32 threads, one per batch row
    float clean[NE] = {0.f, 0.f, 0.f, 0.f};
    float raw[NE]   = {0.f, 0.f, 0.f, 0.f};
    for (int c = 0; c < CIN; ++c) {
        float gx = g_gatex[b * CIN + c];
#pragma unroll
        for (int e = 0; e < NE; ++e) {
            clean[e] = fmaf(gx, w_gate[c * NE + e],  clean[e]);
            raw[e]   = fmaf(gx, w_noise[c * NE + e], raw[e]);
        }
    }
    float nstd[NE], noisy[NE], sm[NE];
    float m = -1e30f;
#pragma unroll
    for (int e = 0; e < NE; ++e) {
        float r  = raw[e];
        float sp = (r > 20.f) ? r : log1pf(expf(r));   // softplus
        nstd[e]  = sp + 0.01f;                          // NOISE_EPS
        noisy[e] = clean[e] + noise[b * NE + e] * nstd[e];
        m = fmaxf(m, noisy[e]);
    }
    float ssum = 0.f;
#pragma unroll
    for (int e = 0; e < NE; ++e) { sm[e] = expf(noisy[e] - m); ssum += sm[e]; }
    float inv = 1.f / ssum;
#pragma unroll
    for (int e = 0; e < NE; ++e) sm[e] *= inv;

    // descending sort of 4 softmaxed logits (strict > keeps earliest index on ties)
    int   idx[4] = {0, 1, 2, 3};
    float v[4]   = {sm[0], sm[1], sm[2], sm[3]};
#pragma unroll
    for (int a = 0; a < 3; ++a)
#pragma unroll
        for (int q = a + 1; q < 4; ++q)
            if (v[q] > v[a]) {
                float tv = v[a]; v[a] = v[q]; v[q] = tv;
                int   ti = idx[a]; idx[a] = idx[q]; idx[q] = ti;
            }

    // top-2 gate weights = softmax(v0, v1)
    float e1 = expf(v[1] - v[0]);
    float gs = 1.f + e1;
    float g0 = 1.f / gs;
    float g1 = e1 / gs;
    g_sel [b * 2 + 0] = idx[0];  g_sel [b * 2 + 1] = idx[1];
    g_selw[b * 2 + 0] = g0;      g_selw[b * 2 + 1] = g1;

    float gates[4] = {0.f, 0.f, 0.f, 0.f};
    gates[idx[0]] = g0;
    gates[idx[1]] = g1;

    float thr_in  = v[2];    // top_vals[:, K]
    float thr_out = v[1];    // top_vals[:, K-1]
    float loadc[4];
#pragma unroll
    for (int e = 0; e < NE; ++e) {
        bool  is_in = noisy[e] > thr_in;
        float thr   = is_in ? thr_in : thr_out;
        float z     = (clean[e] - thr) / nstd[e];
        loadc[e]    = 0.5f * (1.f + erff(z * 0.70710678118654752f));
    }

    // warp-reduce importance & load over the 32 batches
    float imp[4], ld[4];
#pragma unroll
    for (int e = 0; e < NE; ++e) {
        float a = gates[e], l2 = loadc[e];
        for (int off = 16; off; off >>= 1) {
            a  += __shfl_down_sync(0xffffffffu, a,  off);
            l2 += __shfl_down_sync(0xffffffffu, l2, off);
        }
        imp[e] = a; ld[e] = l2;
    }
    if (b == 0)
        out[loss_idx] = 0.01f * (cv_sq4(imp) + cv_sq4(ld));
}

// ---------------- kernel 3: fused sparse conv experts + epilogue ----------
// grid: (NTILES, BQ), 256 threads, 2 CTAs/SM. Block tile: M=128 (Cout) x N=64 (l).
// Thread (og, lg): og = tid>>4 in [0,16), lg = tid&15 in [0,16).
// Per-thread micro-tile: 8 Cout x 4 l.
// Weight staging is register-pipelined: LDGs for channel c+1 issue right after
// the staging barrier of channel c and complete under ~1000 cycles of FFMA.
__global__ void __launch_bounds__(256, 2)
k_conv(const float* __restrict__ x,
       const float* __restrict__ W1,
       const float* __restrict__ b1,
       const float* __restrict__ W2,
       const float* __restrict__ b2,
       float* __restrict__ out)
{
    __shared__ __align__(16) float sw4[16][129][4]; // weights [q=kw/4][o][kw%4], +1 row pad
    __shared__ float sx[144];               // x window: NTILE + KW - 1 = 127 used
    __shared__ float sred[16][NTILE][2];    // partial z reduction [og][l][t]
    __shared__ float sz[2][NTILE];
    __shared__ float ysum[2][NTILE];
    __shared__ float sW2[2][COUT];
    __shared__ float sb1[COUT];

    const int b   = blockIdx.y;
    const int l0  = blockIdx.x * NTILE;
    const int tid = threadIdx.x;
    const int og  = tid >> 4;
    const int lg  = tid & 15;
    const int ob  = og * 8;
    const int lb  = lg * 4;
    // staging coords for this thread's 8 float4 cells
    const int so  = tid >> 4;               // o base pattern: idx2 = tid + r*256
    const int sq  = tid & 15;

    const float* xb = x + (size_t)b * CIN * LIN;

    if (tid < NTILE) { ysum[0][tid] = 0.f; ysum[1][tid] = 0.f; }

    for (int slot = 0; slot < 2; ++slot) {
        const int   e  = g_sel [b * 2 + slot];
        const float gw = g_selw[b * 2 + slot];
        const float* W1e = W1 + (size_t)e * COUT * CIN * KW;

        // per-slot small operands (epilogue)
        sW2[tid >> 7][tid & 127] = W2[e * 2 * COUT + tid];
        if (tid < COUT) sb1[tid] = b1[e * COUT + tid];

        float acc[8][4];
#pragma unroll
        for (int i = 0; i < 8; ++i)
#pragma unroll
            for (int j = 0; j < 4; ++j) acc[i][j] = 0.f;

        // ---- prefetch channel 0 into registers ----
        float4 wreg[8];
        float  xreg = 0.f;
#pragma unroll
        for (int r = 0; r < 8; ++r) {
            int o = so + r * 16;            // (tid + r*256) >> 4
            wreg[r] = *(const float4*)(W1e + ((size_t)o * CIN + 0) * KW + sq * 4);
        }
        if (tid < 128) {
            int l = l0 + tid;
            xreg = (l < LIN) ? xb[l] : 0.f;
        }

        for (int c = 0; c < CIN; ++c) {
            __syncthreads();   // prior compute done reading sx/sw4
            // store prefetched channel c to shared
#pragma unroll
            for (int r = 0; r < 8; ++r) {
                int o = so + r * 16;
                *(float4*)&sw4[sq][o][0] = wreg[r];
            }
            if (tid < 128) sx[tid] = xreg;
            __syncthreads();   // staging visible

            // issue LDGs for channel c+1; latency hidden by compute below
            if (c + 1 < CIN) {
#pragma unroll
                for (int r = 0; r < 8; ++r) {
                    int o = so + r * 16;
                    wreg[r] = *(const float4*)(W1e + ((size_t)o * CIN + (c + 1)) * KW + sq * 4);
                }
                if (tid < 128) {
                    int l = l0 + tid;
                    xreg = (l < LIN) ? xb[(size_t)(c + 1) * LIN + l] : 0.f;
                }
            }

            // shift-register x window + float4 weights, FFMA-bound mainloop
            float xw[7];
#pragma unroll
            for (int t = 0; t < 7; ++t) xw[t] = sx[lb + t];

#pragma unroll 4
            for (int q = 0; q < 16; ++q) {
#pragma unroll
                for (int i = 0; i < 8; ++i) {
                    float4 w = *(const float4*)&sw4[q][ob + i][0];
#pragma unroll
                    for (int j = 0; j < 4; ++j) {
                        acc[i][j] = fmaf(w.x, xw[j],     acc[i][j]);
                        acc[i][j] = fmaf(w.y, xw[j + 1], acc[i][j]);
                        acc[i][j] = fmaf(w.z, xw[j + 2], acc[i][j]);
                        acc[i][j] = fmaf(w.w, xw[j + 3], acc[i][j]);
                    }
                }
                int base = lb + 4 * q;
                xw[0] = xw[4]; xw[1] = xw[5]; xw[2] = xw[6];
                xw[3] = sx[base + 7];
                xw[4] = sx[base + 8];
                xw[5] = sx[base + 9];
                xw[6] = sx[base + 10];   // sx sized 144: in-bounds, dead on last q
            }
        }

        // epilogue: bias + relu + W2 contraction partials
        float p0[4] = {0.f, 0.f, 0.f, 0.f};
        float p1[4] = {0.f, 0.f, 0.f, 0.f};
#pragma unroll
        for (int i = 0; i < 8; ++i) {
            float bb = sb1[ob + i];
            float wa = sW2[0][ob + i];
            float wb = sW2[1][ob + i];
#pragma unroll
            for (int j = 0; j < 4; ++j) {
                float h = fmaxf(acc[i][j] + bb, 0.f);
                p0[j] = fmaf(wa, h, p0[j]);
                p1[j] = fmaf(wb, h, p1[j]);
            }
        }
        __syncthreads();   // make sure prior-slot sred/sz readers are done
#pragma unroll
        for (int j = 0; j < 4; ++j) {
            sred[og][lb + j][0] = p0[j];
            sred[og][lb + j][1] = p1[j];
        }
        __syncthreads();

        // reduce over the 16 og groups
        if (tid < 128) {
            int l = tid & 63, t = tid >> 6;
            float z = b2[e * 2 + t];
#pragma unroll
            for (int o2 = 0; o2 < 16; ++o2) z += sred[o2][l][t];
            sz[t][l] = z;
        }
        __syncthreads();

        // 2-way softmax over t, gate-weighted accumulate
        if (tid < NTILE) {
            float z0 = sz[0][tid], z1 = sz[1][tid];
            float mm = fmaxf(z0, z1);
            float a0 = expf(z0 - mm), a1 = expf(z1 - mm);
            float is = 1.f / (a0 + a1);
            ysum[0][tid] += gw * a0 * is;
            ysum[1][tid] += gw * a1 * is;
        }
        __syncthreads();
    }

    if (tid < 128) {
        int l = tid & 63, t = tid >> 6;
        int gl = l0 + l;
        if (gl < LOUT)
            out[((size_t)b * 2 + t) * LOUT + gl] = ysum[t][l];
    }
}

// ---------------- launcher ------------------------------------------------
extern "C" void kernel_launch(void* const* d_in, const int* in_sizes, int n_in,
                              void* d_out, int out_size)
{
    const float* x       = (const float*)d_in[0];
    const float* noise   = (const float*)d_in[1];
    const float* w_gate  = (const float*)d_in[2];
    const float* w_noise = (const float*)d_in[3];
    const float* W1      = (const float*)d_in[4];
    const float* b1      = (const float*)d_in[5];
    const float* W2      = (const float*)d_in[6];
    const float* b2      = (const float*)d_in[7];
    float* out = (float*)d_out;

    k_gatex<<<BQ, CIN>>>(x);
    k_gate<<<1, 32>>>(noise, w_gate, w_noise, out, out_size - 1);
    dim3 grid(NTILES, BQ);
    k_conv<<<grid, 256>>>(x, W1, b1, W2, b2, out);
}

// round 3
// speedup vs baseline: 3.7153x; 3.7153x over previous
#include <cuda_runtime.h>
#include <math.h>
#include <stdint.h>

#define BQ    32
#define CIN   128
#define LIN   1024
#define NE    4
#define COUT  128
#define KW    64
#define LOUT  961          // 1024 - 64 + 1
#define NTILE 128
#define NTILES 8           // ceil(961/128)
#define SWPAD 68           // W row stride in smem (conflict-free for frag loads)

// ---------------- scratch (device globals: no allocation allowed) ----------
__device__ float g_gatex[BQ * CIN];
__device__ int   g_sel [BQ * 2];
__device__ float g_selw[BQ * 2];

// ---------------- helpers -------------------------------------------------
__device__ __forceinline__ uint32_t f2tf32(float f) {
    uint32_t u;
    asm("cvt.rna.tf32.f32 %0, %1;" : "=r"(u) : "f"(f));
    return u;
}

__device__ __forceinline__ void mma_tf32(float* c,
                                         uint32_t a0, uint32_t a1, uint32_t a2, uint32_t a3,
                                         uint32_t b0, uint32_t b1) {
    asm volatile("mma.sync.aligned.m16n8k8.row.col.f32.tf32.tf32.f32 "
                 "{%0,%1,%2,%3}, {%4,%5,%6,%7}, {%8,%9}, {%0,%1,%2,%3};"
                 : "+f"(c[0]), "+f"(c[1]), "+f"(c[2]), "+f"(c[3])
                 : "r"(a0), "r"(a1), "r"(a2), "r"(a3), "r"(b0), "r"(b1));
}

// ---------------- kernel 1: gate_x = mean over L (warp per row) -----------
__global__ void k_gatex(const float* __restrict__ x) {
    int row  = blockIdx.x * 4 + (threadIdx.x >> 5);   // (b, c) flattened
    int lane = threadIdx.x & 31;
    const float4* xp = (const float4*)(x + (size_t)row * LIN);
    float s = 0.f;
#pragma unroll
    for (int k = 0; k < 8; ++k) {
        float4 v = xp[lane + k * 32];
        s += (v.x + v.y) + (v.z + v.w);
    }
#pragma unroll
    for (int off = 16; off; off >>= 1) s += __shfl_down_sync(0xffffffffu, s, off);
    if (lane == 0) g_gatex[row] = s * (1.0f / (float)LIN);
}

// ---------------- kernel 2: gating, top-k, loss ---------------------------
__device__ __forceinline__ float cv_sq4(const float* w) {
    float mn = 0.25f * (w[0] + w[1] + w[2] + w[3]);
    float s = 0.f;
#pragma unroll
    for (int e = 0; e < 4; ++e) { float d = w[e] - mn; s += d * d; }
    s *= (1.0f / 3.0f);                    // ddof = 1
    return s / (mn * mn + 1e-10f);
}

__global__ void k_gate(const float* __restrict__ noise,
                       const float* __restrict__ w_gate,
                       const float* __restrict__ w_noise,
                       float* __restrict__ out, int loss_idx)
{
    int b = threadIdx.x;                   // 32 threads, one per batch row
    float clean[NE] = {0.f, 0.f, 0.f, 0.f};
    float raw[NE]   = {0.f, 0.f, 0.f, 0.f};
    for (int c = 0; c < CIN; ++c) {
        float gx = g_gatex[b * CIN + c];
#pragma unroll
        for (int e = 0; e < NE; ++e) {
            clean[e] = fmaf(gx, w_gate[c * NE + e],  clean[e]);
            raw[e]   = fmaf(gx, w_noise[c * NE + e], raw[e]);
        }
    }
    float nstd[NE], noisy[NE], sm[NE];
    float m = -1e30f;
#pragma unroll
    for (int e = 0; e < NE; ++e) {
        float r  = raw[e];
        float sp = (r > 20.f) ? r : log1pf(expf(r));   // softplus
        nstd[e]  = sp + 0.01f;                          // NOISE_EPS
        noisy[e] = clean[e] + noise[b * NE + e] * nstd[e];
        m = fmaxf(m, noisy[e]);
    }
    float ssum = 0.f;
#pragma unroll
    for (int e = 0; e < NE; ++e) { sm[e] = expf(noisy[e] - m); ssum += sm[e]; }
    float inv = 1.f / ssum;
#pragma unroll
    for (int e = 0; e < NE; ++e) sm[e] *= inv;

    int   idx[4] = {0, 1, 2, 3};
    float v[4]   = {sm[0], sm[1], sm[2], sm[3]};
#pragma unroll
    for (int a = 0; a < 3; ++a)
#pragma unroll
        for (int q = a + 1; q < 4; ++q)
            if (v[q] > v[a]) {
                float tv = v[a]; v[a] = v[q]; v[q] = tv;
                int   ti = idx[a]; idx[a] = idx[q]; idx[q] = ti;
            }

    float e1 = expf(v[1] - v[0]);
    float gs = 1.f + e1;
    float g0 = 1.f / gs;
    float g1 = e1 / gs;
    g_sel [b * 2 + 0] = idx[0];  g_sel [b * 2 + 1] = idx[1];
    g_selw[b * 2 + 0] = g0;      g_selw[b * 2 + 1] = g1;

    float gates[4] = {0.f, 0.f, 0.f, 0.f};
    gates[idx[0]] = g0;
    gates[idx[1]] = g1;

    float thr_in  = v[2];
    float thr_out = v[1];
    float loadc[4];
#pragma unroll
    for (int e = 0; e < NE; ++e) {
        bool  is_in = noisy[e] > thr_in;
        float thr   = is_in ? thr_in : thr_out;
        float z     = (clean[e] - thr) / nstd[e];
        loadc[e]    = 0.5f * (1.f + erff(z * 0.70710678118654752f));
    }

    float imp[4], ld[4];
#pragma unroll
    for (int e = 0; e < NE; ++e) {
        float a = gates[e], l2 = loadc[e];
        for (int off = 16; off; off >>= 1) {
            a  += __shfl_down_sync(0xffffffffu, a,  off);
            l2 += __shfl_down_sync(0xffffffffu, l2, off);
        }
        imp[e] = a; ld[e] = l2;
    }
    if (b == 0)
        out[loss_idx] = 0.01f * (cv_sq4(imp) + cv_sq4(ld));
}

// ---------------- kernel 3: tf32 tensor-core sparse conv experts ----------
// grid: (NTILES=8, BQ=32), 512 threads (16 warps), 1 CTA/SM.
// CTA tile: M=128 (Cout) x N=128 (l). Warp w: m-rows [(w&7)*16, +16),
// n-half (w>>3)*64. K = Cin*Kw = 8192, looped per channel (64 taps = 8 k-steps).
// mma m16n8k8 tf32: A = W1e rows (smem, stride 68, conflict-free),
// B = x window values from registers (anti-diagonal reuse: 30 regs/channel).
__global__ void __launch_bounds__(512, 1)
k_conv(const float* __restrict__ x,
       const float* __restrict__ W1,
       const float* __restrict__ b1,
       const float* __restrict__ W2,
       const float* __restrict__ b2,
       float* __restrict__ out)
{
    __shared__ __align__(16) uint32_t sw[COUT * SWPAD];   // 34816 B (tf32 bits)
    __shared__ uint32_t sx[192];                          // x window tf32, 191 used
    __shared__ float sred[16][4][32];                     // 8 KB epilogue partials
    __shared__ float sz[2][NTILE];
    __shared__ float ysum[2][NTILE];
    __shared__ float sW2[2][COUT];
    __shared__ float sb1[COUT];

    const int b    = blockIdx.y;
    const int l0   = blockIdx.x * NTILE;
    const int tid  = threadIdx.x;
    const int warp = tid >> 5;
    const int lane = tid & 31;
    const int g    = lane >> 2;
    const int t4   = lane & 3;
    const int m0   = (warp & 7) * 16;
    const int nhalf= warp >> 3;
    const int rlo  = m0 + g;
    const int rhi  = m0 + g + 8;
    const int so   = tid >> 4;          // W staging: o base (idx2 = tid + r*512)
    const int sq   = tid & 15;          // W staging: kw quad

    const float* xb = x + (size_t)b * CIN * LIN;

    if (tid < 2 * NTILE) ysum[tid >> 7][tid & 127] = 0.f;

    for (int slot = 0; slot < 2; ++slot) {
        const int   e  = g_sel [b * 2 + slot];
        const float gw = g_selw[b * 2 + slot];
        const float* W1e = W1 + (size_t)e * COUT * CIN * KW;

        if (tid < 2 * COUT) sW2[tid >> 7][tid & 127] = W2[e * 2 * COUT + tid];
        if (tid < COUT)     sb1[tid] = b1[e * COUT + tid];

        float acc[8][4];
#pragma unroll
        for (int i = 0; i < 8; ++i)
#pragma unroll
            for (int j = 0; j < 4; ++j) acc[i][j] = 0.f;

        // ---- prefetch channel 0 ----
        float4 wreg[4];
        float  xreg = 0.f;
#pragma unroll
        for (int r = 0; r < 4; ++r) {
            int o = so + r * 32;        // (tid + r*512) >> 4
            wreg[r] = *(const float4*)(W1e + ((size_t)o * CIN + 0) * KW + sq * 4);
        }
        if (tid < 192) {
            int l = l0 + tid;
            xreg = (l < LIN) ? xb[l] : 0.f;
        }

        for (int c = 0; c < CIN; ++c) {
            __syncthreads();            // prior compute done reading sw/sx
            // store channel c (convert to tf32 bit patterns)
#pragma unroll
            for (int r = 0; r < 4; ++r) {
                int o = so + r * 32;
                uint4 u;
                u.x = f2tf32(wreg[r].x); u.y = f2tf32(wreg[r].y);
                u.z = f2tf32(wreg[r].z); u.w = f2tf32(wreg[r].w);
                *(uint4*)&sw[o * SWPAD + sq * 4] = u;
            }
            if (tid < 192) sx[tid] = f2tf32(xreg);
            __syncthreads();            // staging visible

            // prefetch channel c+1 (latency hidden under HMMA below)
            if (c + 1 < CIN) {
#pragma unroll
                for (int r = 0; r < 4; ++r) {
                    int o = so + r * 32;
                    wreg[r] = *(const float4*)(W1e + ((size_t)o * CIN + (c + 1)) * KW + sq * 4);
                }
                if (tid < 192) {
                    int l = l0 + tid;
                    xreg = (l < 192 + l0 && l < LIN) ? xb[(size_t)(c + 1) * LIN + l] : 0.f;
                }
            }

            // B window: all values this thread needs this channel (30 regs)
            uint32_t bwin[30];
            const int bbase = nhalf * 64 + g + t4;
#pragma unroll
            for (int j = 0; j < 30; ++j) bwin[j] = sx[bbase + 4 * j];

#pragma unroll
            for (int kk = 0; kk < 8; ++kk) {
                const uint32_t* swr = &sw[kk * 8 + t4];
                uint32_t a0 = swr[rlo * SWPAD];
                uint32_t a1 = swr[rhi * SWPAD];
                uint32_t a2 = swr[rlo * SWPAD + 4];
                uint32_t a3 = swr[rhi * SWPAD + 4];
#pragma unroll
                for (int nb = 0; nb < 8; ++nb) {
                    int s = kk + nb;
                    mma_tf32(acc[nb], a0, a1, a2, a3, bwin[2 * s], bwin[2 * s + 1]);
                }
            }
        }

        // ---- epilogue: bias + relu + W2 partials, reduce over Cout ----
        float b1lo = sb1[rlo], b1hi = sb1[rhi];
        float w2lo0 = sW2[0][rlo], w2hi0 = sW2[0][rhi];
        float w2lo1 = sW2[1][rlo], w2hi1 = sW2[1][rhi];
        float p[32];                    // [nb][r][t] flattened: nb*4 + r*2 + t
#pragma unroll
        for (int nb = 0; nb < 8; ++nb) {
            float h00 = fmaxf(acc[nb][0] + b1lo, 0.f);   // (rlo, col even)
            float h01 = fmaxf(acc[nb][1] + b1lo, 0.f);   // (rlo, col odd)
            float h10 = fmaxf(acc[nb][2] + b1hi, 0.f);   // (rhi, col even)
            float h11 = fmaxf(acc[nb][3] + b1hi, 0.f);   // (rhi, col odd)
            p[nb * 4 + 0] = fmaf(w2lo0, h00, w2hi0 * h10);
            p[nb * 4 + 1] = fmaf(w2lo1, h00, w2hi1 * h10);
            p[nb * 4 + 2] = fmaf(w2lo0, h01, w2hi0 * h11);
            p[nb * 4 + 3] = fmaf(w2lo1, h01, w2hi1 * h11);
        }
        // reduce over g (8 lanes with same t4)
#pragma unroll
        for (int j = 0; j < 32; ++j) {
            p[j] += __shfl_down_sync(0xffffffffu, p[j], 16);
            p[j] += __shfl_down_sync(0xffffffffu, p[j], 8);
            p[j] += __shfl_down_sync(0xffffffffu, p[j], 4);
        }
        __syncthreads();                // sred free from prior use
        if (lane < 4) {
#pragma unroll
            for (int j = 0; j < 32; ++j) sred[warp][lane][j] = p[j];
        }
        __syncthreads();

        // z[t][col]: sum 8 warps of the matching n-half
        if (tid < 2 * NTILE) {
            int t   = tid >> 7;
            int col = tid & 127;
            int nh  = col >> 6;
            int ch  = col & 63;
            int nb  = ch >> 3;
            int tt4 = (ch >> 1) & 3;
            int r   = ch & 1;
            int pj  = nb * 4 + r * 2 + t;
            float z = b2[e * 2 + t];
#pragma unroll
            for (int w8 = 0; w8 < 8; ++w8) z += sred[nh * 8 + w8][tt4][pj];
            sz[t][col] = z;
        }
        __syncthreads();

        // 2-way softmax over t, gate-weighted accumulate
        if (tid < NTILE) {
            float z0 = sz[0][tid], z1 = sz[1][tid];
            float mm = fmaxf(z0, z1);
            float a0 = expf(z0 - mm), a1 = expf(z1 - mm);
            float is = 1.f / (a0 + a1);
            ysum[0][tid] += gw * a0 * is;
            ysum[1][tid] += gw * a1 * is;
        }
        __syncthreads();
    }

    if (tid < 2 * NTILE) {
        int t = tid >> 7, l = tid & 127;
        int gl = l0 + l;
        if (gl < LOUT)
            out[((size_t)b * 2 + t) * LOUT + gl] = ysum[t][l];
    }
}

// ---------------- launcher ------------------------------------------------
extern "C" void kernel_launch(void* const* d_in, const int* in_sizes, int n_in,
                              void* d_out, int out_size)
{
    const float* x       = (const float*)d_in[0];
    const float* noise   = (const float*)d_in[1];
    const float* w_gate  = (const float*)d_in[2];
    const float* w_noise = (const float*)d_in[3];
    const float* W1      = (const float*)d_in[4];
    const float* b1      = (const float*)d_in[5];
    const float* W2      = (const float*)d_in[6];
    const float* b2      = (const float*)d_in[7];
    float* out = (float*)d_out;

    k_gatex<<<BQ * CIN / 4, 128>>>(x);
    k_gate<<<1, 32>>>(noise, w_gate, w_noise, out, out_size - 1);
    dim3 grid(NTILES, BQ);
    k_conv<<<grid, 512>>>(x, W1, b1, W2, b2, out);
}

// round 4
// speedup vs baseline: 6.1253x; 1.6487x over previous
#include <cuda_runtime.h>
#include <math.h>
#include <stdint.h>

#define BQ    32
#define CIN   128
#define LIN   1024
#define NE    4
#define COUT  128
#define KW    64
#define LOUT  961          // 1024 - 64 + 1
#define NTILE 112
#define NTILES 9           // 9*112 = 1008 >= 961; 288 CTAs ~ 97% of 2 waves
#define SWPAD 36           // W pair-row stride (words): banks (4g+t4)&31 distinct
#define WNDW  176          // x window: NTILE + KW - 1 = 175, rounded up

// ---------------- scratch (device globals: no allocation allowed) ----------
__device__ float g_gatex[BQ * CIN];
__device__ int   g_sel [BQ * 2];
__device__ float g_selw[BQ * 2];

// ---------------- helpers -------------------------------------------------
__device__ __forceinline__ uint32_t pack_bf16x2(float lo, float hi) {
    uint32_t r;
    asm("cvt.rn.bf16x2.f32 %0, %1, %2;" : "=r"(r) : "f"(hi), "f"(lo));
    return r;
}

__device__ __forceinline__ void mma_bf16(float* c,
                                         uint32_t a0, uint32_t a1, uint32_t a2, uint32_t a3,
                                         uint32_t b0, uint32_t b1) {
    asm volatile("mma.sync.aligned.m16n8k16.row.col.f32.bf16.bf16.f32 "
                 "{%0,%1,%2,%3}, {%4,%5,%6,%7}, {%8,%9}, {%0,%1,%2,%3};"
                 : "+f"(c[0]), "+f"(c[1]), "+f"(c[2]), "+f"(c[3])
                 : "r"(a0), "r"(a1), "r"(a2), "r"(a3), "r"(b0), "r"(b1));
}

// ---------------- kernel 1: gate_x = mean over L (warp per row) -----------
__global__ void k_gatex(const float* __restrict__ x) {
    int row  = blockIdx.x * 4 + (threadIdx.x >> 5);   // (b, c) flattened
    int lane = threadIdx.x & 31;
    const float4* xp = (const float4*)(x + (size_t)row * LIN);
    float s = 0.f;
#pragma unroll
    for (int k = 0; k < 8; ++k) {
        float4 v = xp[lane + k * 32];
        s += (v.x + v.y) + (v.z + v.w);
    }
#pragma unroll
    for (int off = 16; off; off >>= 1) s += __shfl_down_sync(0xffffffffu, s, off);
    if (lane == 0) g_gatex[row] = s * (1.0f / (float)LIN);
}

// ---------------- kernel 2: gating, top-k, loss ---------------------------
__device__ __forceinline__ float cv_sq4(const float* w) {
    float mn = 0.25f * (w[0] + w[1] + w[2] + w[3]);
    float s = 0.f;
#pragma unroll
    for (int e = 0; e < 4; ++e) { float d = w[e] - mn; s += d * d; }
    s *= (1.0f / 3.0f);                    // ddof = 1
    return s / (mn * mn + 1e-10f);
}

__global__ void k_gate(const float* __restrict__ noise,
                       const float* __restrict__ w_gate,
                       const float* __restrict__ w_noise,
                       float* __restrict__ out, int loss_idx)
{
    int b = threadIdx.x;                   // 32 threads, one per batch row
    float clean[NE] = {0.f, 0.f, 0.f, 0.f};
    float raw[NE]   = {0.f, 0.f, 0.f, 0.f};
    for (int c = 0; c < CIN; ++c) {
        float gx = g_gatex[b * CIN + c];
#pragma unroll
        for (int e = 0; e < NE; ++e) {
            clean[e] = fmaf(gx, w_gate[c * NE + e],  clean[e]);
            raw[e]   = fmaf(gx, w_noise[c * NE + e], raw[e]);
        }
    }
    float nstd[NE], noisy[NE], sm[NE];
    float m = -1e30f;
#pragma unroll
    for (int e = 0; e < NE; ++e) {
        float r  = raw[e];
        float sp = (r > 20.f) ? r : log1pf(expf(r));   // softplus
        nstd[e]  = sp + 0.01f;                          // NOISE_EPS
        noisy[e] = clean[e] + noise[b * NE + e] * nstd[e];
        m = fmaxf(m, noisy[e]);
    }
    float ssum = 0.f;
#pragma unroll
    for (int e = 0; e < NE; ++e) { sm[e] = expf(noisy[e] - m); ssum += sm[e]; }
    float inv = 1.f / ssum;
#pragma unroll
    for (int e = 0; e < NE; ++e) sm[e] *= inv;

    int   idx[4] = {0, 1, 2, 3};
    float v[4]   = {sm[0], sm[1], sm[2], sm[3]};
#pragma unroll
    for (int a = 0; a < 3; ++a)
#pragma unroll
        for (int q = a + 1; q < 4; ++q)
            if (v[q] > v[a]) {
                float tv = v[a]; v[a] = v[q]; v[q] = tv;
                int   ti = idx[a]; idx[a] = idx[q]; idx[q] = ti;
            }

    float e1 = expf(v[1] - v[0]);
    float gs = 1.f + e1;
    float g0 = 1.f / gs;
    float g1 = e1 / gs;
    g_sel [b * 2 + 0] = idx[0];  g_sel [b * 2 + 1] = idx[1];
    g_selw[b * 2 + 0] = g0;      g_selw[b * 2 + 1] = g1;

    float gates[4] = {0.f, 0.f, 0.f, 0.f};
    gates[idx[0]] = g0;
    gates[idx[1]] = g1;

    float thr_in  = v[2];
    float thr_out = v[1];
    float loadc[4];
#pragma unroll
    for (int e = 0; e < NE; ++e) {
        bool  is_in = noisy[e] > thr_in;
        float thr   = is_in ? thr_in : thr_out;
        float z     = (clean[e] - thr) / nstd[e];
        loadc[e]    = 0.5f * (1.f + erff(z * 0.70710678118654752f));
    }

    float imp[4], ld[4];
#pragma unroll
    for (int e = 0; e < NE; ++e) {
        float a = gates[e], l2 = loadc[e];
        for (int off = 16; off; off >>= 1) {
            a  += __shfl_down_sync(0xffffffffu, a,  off);
            l2 += __shfl_down_sync(0xffffffffu, l2, off);
        }
        imp[e] = a; ld[e] = l2;
    }
    if (b == 0)
        out[loss_idx] = 0.01f * (cv_sq4(imp) + cv_sq4(ld));
}

// ---------------- kernel 3: bf16 tensor-core sparse conv experts ----------
// grid: (NTILES=9, BQ=32) = 288 CTAs, 512 threads (16 warps), 1 CTA/SM.
// CTA tile: M=128 (Cout) x N=112 (l). Warp w: m-rows [(w&7)*16, +16),
// n-half (w>>3)*56. K = Cin*Kw, per channel 64 taps = 4 k16-steps.
// mma m16n8k16 bf16: A = W1e pairs (smem stride 36 words, conflict-free),
// B = x pairs from registers (anti-diagonal reuse: 14 bf16x2 per channel).
__global__ void __launch_bounds__(512, 1)
k_conv(const float* __restrict__ x,
       const float* __restrict__ W1,
       const float* __restrict__ b1,
       const float* __restrict__ W2,
       const float* __restrict__ b2,
       float* __restrict__ out)
{
    __shared__ __align__(16) uint32_t sw[COUT * SWPAD]; // bf16x2 pairs, 18.4KB
    __shared__ float sxf[WNDW];                         // x window fp32
    __shared__ float sred[16][4][28];                   // epilogue partials
    __shared__ float sz[2][NTILE];
    __shared__ float ysum[2][NTILE];
    __shared__ float sW2[2][COUT];
    __shared__ float sb1[COUT];

    const int b    = blockIdx.y;
    const int l0   = blockIdx.x * NTILE;
    const int tid  = threadIdx.x;
    const int warp = tid >> 5;
    const int lane = tid & 31;
    const int g    = lane >> 2;
    const int t4   = lane & 3;
    const int m0   = (warp & 7) * 16;
    const int nhalf= warp >> 3;
    const int rlo  = m0 + g;
    const int rhi  = m0 + g + 8;
    const int so   = tid >> 4;          // W staging: o base (o = so + r*32)
    const int sq   = tid & 15;          // W staging: tap quad [4sq, 4sq+4)

    const float* xb = x + (size_t)b * CIN * LIN;

    if (tid < 2 * NTILE) {
        int t = tid >= NTILE;
        ysum[t][tid - t * NTILE] = 0.f;
    }

    for (int slot = 0; slot < 2; ++slot) {
        const int   e  = g_sel [b * 2 + slot];
        const float gw = g_selw[b * 2 + slot];
        const float* W1e = W1 + (size_t)e * COUT * CIN * KW;

        if (tid < 2 * COUT) sW2[tid >> 7][tid & 127] = W2[e * 2 * COUT + tid];
        if (tid < COUT)     sb1[tid] = b1[e * COUT + tid];

        float acc[7][4];
#pragma unroll
        for (int i = 0; i < 7; ++i)
#pragma unroll
            for (int j = 0; j < 4; ++j) acc[i][j] = 0.f;

        // ---- prefetch channel 0 ----
        float4 wreg[4];
        float  xreg = 0.f;
#pragma unroll
        for (int r = 0; r < 4; ++r) {
            int o = so + r * 32;
            wreg[r] = *(const float4*)(W1e + ((size_t)o * CIN + 0) * KW + sq * 4);
        }
        if (tid < WNDW) {
            int l = l0 + tid;
            xreg = (l < LIN) ? xb[l] : 0.f;
        }

        for (int c = 0; c < CIN; ++c) {
            __syncthreads();            // prior compute done reading sw/sxf
            // store channel c as bf16x2 pairs (pair p = taps 2p, 2p+1)
#pragma unroll
            for (int r = 0; r < 4; ++r) {
                int o = so + r * 32;
                uint2 u;
                u.x = pack_bf16x2(wreg[r].x, wreg[r].y);
                u.y = pack_bf16x2(wreg[r].z, wreg[r].w);
                *(uint2*)&sw[o * SWPAD + sq * 2] = u;
            }
            if (tid < WNDW) sxf[tid] = xreg;
            __syncthreads();            // staging visible

            // prefetch channel c+1 (latency hidden under HMMA below)
            if (c + 1 < CIN) {
#pragma unroll
                for (int r = 0; r < 4; ++r) {
                    int o = so + r * 32;
                    wreg[r] = *(const float4*)(W1e + ((size_t)o * CIN + (c + 1)) * KW + sq * 4);
                }
                if (tid < WNDW) {
                    int l = l0 + tid;
                    xreg = (l < LIN) ? xb[(size_t)(c + 1) * LIN + l] : 0.f;
                }
            }

            // B pairs for this channel: P[j] = {x[p], x[p+1]}, p = bbase + 8j.
            // b(kk, nb, lo) = P[2kk+nb], b(kk, nb, hi/+8) = P[2kk+nb+1].
            uint32_t P[14];
            const int bbase = nhalf * 56 + g + 2 * t4;
#pragma unroll
            for (int j = 0; j < 14; ++j)
                P[j] = pack_bf16x2(sxf[bbase + 8 * j], sxf[bbase + 8 * j + 1]);

#pragma unroll
            for (int kk = 0; kk < 4; ++kk) {
                const uint32_t* swr = &sw[kk * 8 + t4];
                uint32_t a0 = swr[rlo * SWPAD];
                uint32_t a1 = swr[rhi * SWPAD];
                uint32_t a2 = swr[rlo * SWPAD + 4];
                uint32_t a3 = swr[rhi * SWPAD + 4];
#pragma unroll
                for (int nb = 0; nb < 7; ++nb) {
                    int s = 2 * kk + nb;
                    mma_bf16(acc[nb], a0, a1, a2, a3, P[s], P[s + 1]);
                }
            }
        }

        // ---- epilogue: bias + relu + W2 partials, reduce over Cout ----
        float b1lo = sb1[rlo], b1hi = sb1[rhi];
        float w2lo0 = sW2[0][rlo], w2hi0 = sW2[0][rhi];
        float w2lo1 = sW2[1][rlo], w2hi1 = sW2[1][rhi];
        float p[28];                    // [nb*4 + r*2 + t], r = col parity
#pragma unroll
        for (int nb = 0; nb < 7; ++nb) {
            float h00 = fmaxf(acc[nb][0] + b1lo, 0.f);   // (rlo, col even)
            float h01 = fmaxf(acc[nb][1] + b1lo, 0.f);   // (rlo, col odd)
            float h10 = fmaxf(acc[nb][2] + b1hi, 0.f);   // (rhi, col even)
            float h11 = fmaxf(acc[nb][3] + b1hi, 0.f);   // (rhi, col odd)
            p[nb * 4 + 0] = fmaf(w2lo0, h00, w2hi0 * h10);
            p[nb * 4 + 1] = fmaf(w2lo1, h00, w2hi1 * h10);
            p[nb * 4 + 2] = fmaf(w2lo0, h01, w2hi0 * h11);
            p[nb * 4 + 3] = fmaf(w2lo1, h01, w2hi1 * h11);
        }
        // reduce over g (8 lanes sharing t4)
#pragma unroll
        for (int j = 0; j < 28; ++j) {
            p[j] += __shfl_down_sync(0xffffffffu, p[j], 16);
            p[j] += __shfl_down_sync(0xffffffffu, p[j], 8);
            p[j] += __shfl_down_sync(0xffffffffu, p[j], 4);
        }
        __syncthreads();                // sred free from prior use
        if (lane < 4) {
#pragma unroll
            for (int j = 0; j < 28; ++j) sred[warp][lane][j] = p[j];
        }
        __syncthreads();

        // z[t][col]: sum 8 warps of the matching n-half
        if (tid < 2 * NTILE) {
            int t   = tid >= NTILE;
            int col = tid - t * NTILE;
            int nh  = col >= 56;
            int ch  = col - nh * 56;
            int nb  = ch >> 3;
            int tt4 = (ch >> 1) & 3;
            int r   = ch & 1;
            int pj  = nb * 4 + r * 2 + t;
            float z = b2[e * 2 + t];
#pragma unroll
            for (int w8 = 0; w8 < 8; ++w8) z += sred[nh * 8 + w8][tt4][pj];
            sz[t][col] = z;
        }
        __syncthreads();

        // 2-way softmax over t, gate-weighted accumulate
        if (tid < NTILE) {
            float z0 = sz[0][tid], z1 = sz[1][tid];
            float mm = fmaxf(z0, z1);
            float a0 = expf(z0 - mm), a1 = expf(z1 - mm);
            float is = 1.f / (a0 + a1);
            ysum[0][tid] += gw * a0 * is;
            ysum[1][tid] += gw * a1 * is;
        }
        __syncthreads();
    }

    if (tid < 2 * NTILE) {
        int t = tid >= NTILE, l = tid - t * NTILE;
        int gl = l0 + l;
        if (gl < LOUT)
            out[((size_t)b * 2 + t) * LOUT + gl] = ysum[t][l];
    }
}

// ---------------- launcher ------------------------------------------------
extern "C" void kernel_launch(void* const* d_in, const int* in_sizes, int n_in,
                              void* d_out, int out_size)
{
    const float* x       = (const float*)d_in[0];
    const float* noise   = (const float*)d_in[1];
    const float* w_gate  = (const float*)d_in[2];
    const float* w_noise = (const float*)d_in[3];
    const float* W1      = (const float*)d_in[4];
    const float* b1      = (const float*)d_in[5];
    const float* W2      = (const float*)d_in[6];
    const float* b2      = (const float*)d_in[7];
    float* out = (float*)d_out;

    k_gatex<<<BQ * CIN / 4, 128>>>(x);
    k_gate<<<1, 32>>>(noise, w_gate, w_noise, out, out_size - 1);
    dim3 grid(NTILES, BQ);
    k_conv<<<grid, 512>>>(x, W1, b1, W2, b2, out);
}

// round 5
// speedup vs baseline: 7.2299x; 1.1803x over previous
#include <cuda_runtime.h>
#include <math.h>
#include <stdint.h>

#define BQ    32
#define CIN   128
#define LIN   1024
#define NE    4
#define COUT  128
#define KW    64
#define LOUT  961          // 1024 - 64 + 1
#define NTILE 112
#define NTILES 9           // 9*112 = 1008 >= 961; 288 CTAs ~ 97% of 2 waves
#define SWPAD 36           // W pair-row stride (words): banks (4g+t4)&31 distinct
#define WNDW  176          // x window: NTILE + KW - 1 = 175, rounded up

// ---------------- scratch (device globals: no allocation allowed) ----------
__device__ float g_gatex[BQ * CIN];
__device__ int   g_sel [BQ * 2];
__device__ float g_selw[BQ * 2];

// ---------------- helpers -------------------------------------------------
__device__ __forceinline__ uint32_t pack_f16x2(float lo, float hi) {
    uint32_t r;
    asm("cvt.rn.f16x2.f32 %0, %1, %2;" : "=r"(r) : "f"(hi), "f"(lo));
    return r;
}

__device__ __forceinline__ void mma_f16(float* c,
                                        uint32_t a0, uint32_t a1, uint32_t a2, uint32_t a3,
                                        uint32_t b0, uint32_t b1) {
    asm volatile("mma.sync.aligned.m16n8k16.row.col.f32.f16.f16.f32 "
                 "{%0,%1,%2,%3}, {%4,%5,%6,%7}, {%8,%9}, {%0,%1,%2,%3};"
                 : "+f"(c[0]), "+f"(c[1]), "+f"(c[2]), "+f"(c[3])
                 : "r"(a0), "r"(a1), "r"(a2), "r"(a3), "r"(b0), "r"(b1));
}

// ---------------- kernel 1: gate_x = mean over L (warp per row) -----------
__global__ void k_gatex(const float* __restrict__ x) {
    int row  = blockIdx.x * 4 + (threadIdx.x >> 5);   // (b, c) flattened
    int lane = threadIdx.x & 31;
    const float4* xp = (const float4*)(x + (size_t)row * LIN);
    float s = 0.f;
#pragma unroll
    for (int k = 0; k < 8; ++k) {
        float4 v = xp[lane + k * 32];
        s += (v.x + v.y) + (v.z + v.w);
    }
#pragma unroll
    for (int off = 16; off; off >>= 1) s += __shfl_down_sync(0xffffffffu, s, off);
    if (lane == 0) g_gatex[row] = s * (1.0f / (float)LIN);
}

// ---------------- kernel 2: gating, top-k, loss ---------------------------
__device__ __forceinline__ float cv_sq4(const float* w) {
    float mn = 0.25f * (w[0] + w[1] + w[2] + w[3]);
    float s = 0.f;
#pragma unroll
    for (int e = 0; e < 4; ++e) { float d = w[e] - mn; s += d * d; }
    s *= (1.0f / 3.0f);                    // ddof = 1
    return s / (mn * mn + 1e-10f);
}

__global__ void k_gate(const float* __restrict__ noise,
                       const float* __restrict__ w_gate,
                       const float* __restrict__ w_noise,
                       float* __restrict__ out, int loss_idx)
{
    int b = threadIdx.x;                   // 32 threads, one per batch row
    float clean[NE] = {0.f, 0.f, 0.f, 0.f};
    float raw[NE]   = {0.f, 0.f, 0.f, 0.f};
    for (int c = 0; c < CIN; ++c) {
        float gx = g_gatex[b * CIN + c];
#pragma unroll
        for (int e = 0; e < NE; ++e) {
            clean[e] = fmaf(gx, w_gate[c * NE + e],  clean[e]);
            raw[e]   = fmaf(gx, w_noise[c * NE + e], raw[e]);
        }
    }
    float nstd[NE], noisy[NE], sm[NE];
    float m = -1e30f;
#pragma unroll
    for (int e = 0; e < NE; ++e) {
        float r  = raw[e];
        float sp = (r > 20.f) ? r : log1pf(expf(r));   // softplus
        nstd[e]  = sp + 0.01f;                          // NOISE_EPS
        noisy[e] = clean[e] + noise[b * NE + e] * nstd[e];
        m = fmaxf(m, noisy[e]);
    }
    float ssum = 0.f;
#pragma unroll
    for (int e = 0; e < NE; ++e) { sm[e] = expf(noisy[e] - m); ssum += sm[e]; }
    float inv = 1.f / ssum;
#pragma unroll
    for (int e = 0; e < NE; ++e) sm[e] *= inv;

    int   idx[4] = {0, 1, 2, 3};
    float v[4]   = {sm[0], sm[1], sm[2], sm[3]};
#pragma unroll
    for (int a = 0; a < 3; ++a)
#pragma unroll
        for (int q = a + 1; q < 4; ++q)
            if (v[q] > v[a]) {
                float tv = v[a]; v[a] = v[q]; v[q] = tv;
                int   ti = idx[a]; idx[a] = idx[q]; idx[q] = ti;
            }

    float e1 = expf(v[1] - v[0]);
    float gs = 1.f + e1;
    float g0 = 1.f / gs;
    float g1 = e1 / gs;
    g_sel [b * 2 + 0] = idx[0];  g_sel [b * 2 + 1] = idx[1];
    g_selw[b * 2 + 0] = g0;      g_selw[b * 2 + 1] = g1;

    float gates[4] = {0.f, 0.f, 0.f, 0.f};
    gates[idx[0]] = g0;
    gates[idx[1]] = g1;

    float thr_in  = v[2];
    float thr_out = v[1];
    float loadc[4];
#pragma unroll
    for (int e = 0; e < NE; ++e) {
        bool  is_in = noisy[e] > thr_in;
        float thr   = is_in ? thr_in : thr_out;
        float z     = (clean[e] - thr) / nstd[e];
        loadc[e]    = 0.5f * (1.f + erff(z * 0.70710678118654752f));
    }

    float imp[4], ld[4];
#pragma unroll
    for (int e = 0; e < NE; ++e) {
        float a = gates[e], l2 = loadc[e];
        for (int off = 16; off; off >>= 1) {
            a  += __shfl_down_sync(0xffffffffu, a,  off);
            l2 += __shfl_down_sync(0xffffffffu, l2, off);
        }
        imp[e] = a; ld[e] = l2;
    }
    if (b == 0)
        out[loss_idx] = 0.01f * (cv_sq4(imp) + cv_sq4(ld));
}

// ---------------- kernel 3: fp16 tensor-core sparse conv experts ----------
// grid: (NTILES=9, BQ=32) = 288 CTAs, 512 threads (16 warps), 1 CTA/SM.
// CTA tile: M=128 (Cout) x N=112 (l). Warp w: m-rows [(w&7)*16, +16),
// n-half (w>>3)*56. Per channel: 64 taps = 4 k16-steps.
// mma m16n8k16 f16 (fp32 accum): A = W1e tap-pairs (smem stride 36 words,
// conflict-free), B = pre-paired x window sxp[p] = {x[p], x[p+1]} (f16x2):
// one LDS.32 per fragment half, anti-diagonal reuse = 14 loads per channel.
__global__ void __launch_bounds__(512, 1)
k_conv(const float* __restrict__ x,
       const float* __restrict__ W1,
       const float* __restrict__ b1,
       const float* __restrict__ W2,
       const float* __restrict__ b2,
       float* __restrict__ out)
{
    __shared__ __align__(16) uint32_t sw[COUT * SWPAD]; // f16x2 tap pairs, 18.4KB
    __shared__ uint32_t sxp[WNDW];                      // paired x window f16x2
    __shared__ float sred[16][4][28];                   // epilogue partials
    __shared__ float sz[2][NTILE];
    __shared__ float ysum[2][NTILE];
    __shared__ float sW2[2][COUT];
    __shared__ float sb1[COUT];

    const int b    = blockIdx.y;
    const int l0   = blockIdx.x * NTILE;
    const int tid  = threadIdx.x;
    const int warp = tid >> 5;
    const int lane = tid & 31;
    const int g    = lane >> 2;
    const int t4   = lane & 3;
    const int m0   = (warp & 7) * 16;
    const int nhalf= warp >> 3;
    const int rlo  = m0 + g;
    const int rhi  = m0 + g + 8;
    const int so   = tid >> 4;          // W staging: o base (o = so + r*32)
    const int sq   = tid & 15;          // W staging: tap quad [4sq, 4sq+4)

    const float* xb = x + (size_t)b * CIN * LIN;

    if (tid < 2 * NTILE) {
        int t = tid >= NTILE;
        ysum[t][tid - t * NTILE] = 0.f;
    }

    for (int slot = 0; slot < 2; ++slot) {
        const int   e  = g_sel [b * 2 + slot];
        const float gw = g_selw[b * 2 + slot];
        const float* W1e = W1 + (size_t)e * COUT * CIN * KW;

        if (tid < 2 * COUT) sW2[tid >> 7][tid & 127] = W2[e * 2 * COUT + tid];
        if (tid < COUT)     sb1[tid] = b1[e * COUT + tid];

        float acc[7][4];
#pragma unroll
        for (int i = 0; i < 7; ++i)
#pragma unroll
            for (int j = 0; j < 4; ++j) acc[i][j] = 0.f;

        // ---- prefetch channel 0 ----
        float4 wreg[4];
        float  xra = 0.f, xrb = 0.f;
#pragma unroll
        for (int r = 0; r < 4; ++r) {
            int o = so + r * 32;
            wreg[r] = *(const float4*)(W1e + ((size_t)o * CIN + 0) * KW + sq * 4);
        }
        if (tid < WNDW) {
            int l = l0 + tid;
            xra = (l < LIN)     ? xb[l]     : 0.f;
            xrb = (l + 1 < LIN) ? xb[l + 1] : 0.f;   // same L1 line
        }

        for (int c = 0; c < CIN; ++c) {
            __syncthreads();            // prior compute done reading sw/sxp
            // store channel c as f16x2 pairs (pair p = taps 2p, 2p+1)
#pragma unroll
            for (int r = 0; r < 4; ++r) {
                int o = so + r * 32;
                uint2 u;
                u.x = pack_f16x2(wreg[r].x, wreg[r].y);
                u.y = pack_f16x2(wreg[r].z, wreg[r].w);
                *(uint2*)&sw[o * SWPAD + sq * 2] = u;
            }
            if (tid < WNDW) sxp[tid] = pack_f16x2(xra, xrb);
            __syncthreads();            // staging visible

            // prefetch channel c+1 (latency hidden under HMMA below)
            if (c + 1 < CIN) {
                const float* xc = xb + (size_t)(c + 1) * LIN;
#pragma unroll
                for (int r = 0; r < 4; ++r) {
                    int o = so + r * 32;
                    wreg[r] = *(const float4*)(W1e + ((size_t)o * CIN + (c + 1)) * KW + sq * 4);
                }
                if (tid < WNDW) {
                    int l = l0 + tid;
                    xra = (l < LIN)     ? xc[l]     : 0.f;
                    xrb = (l + 1 < LIN) ? xc[l + 1] : 0.f;
                }
            }

            // B pairs: P[j] = sxp[bbase + 8j] = {x[p], x[p+1]}, one LDS each.
            // b(kk, nb, lo) = P[2kk+nb], b(kk, nb, hi/+8) = P[2kk+nb+1].
            uint32_t P[14];
            const int bbase = nhalf * 56 + g + 2 * t4;
#pragma unroll
            for (int j = 0; j < 14; ++j) P[j] = sxp[bbase + 8 * j];

#pragma unroll
            for (int kk = 0; kk < 4; ++kk) {
                const uint32_t* swr = &sw[kk * 8 + t4];
                uint32_t a0 = swr[rlo * SWPAD];
                uint32_t a1 = swr[rhi * SWPAD];
                uint32_t a2 = swr[rlo * SWPAD + 4];
                uint32_t a3 = swr[rhi * SWPAD + 4];
#pragma unroll
                for (int nb = 0; nb < 7; ++nb) {
                    int s = 2 * kk + nb;
                    mma_f16(acc[nb], a0, a1, a2, a3, P[s], P[s + 1]);
                }
            }
        }

        // ---- epilogue: bias + relu + W2 partials, reduce over Cout ----
        float b1lo = sb1[rlo], b1hi = sb1[rhi];
        float w2lo0 = sW2[0][rlo], w2hi0 = sW2[0][rhi];
        float w2lo1 = sW2[1][rlo], w2hi1 = sW2[1][rhi];
        float p[28];                    // [nb*4 + r*2 + t], r = col parity
#pragma unroll
        for (int nb = 0; nb < 7; ++nb) {
            float h00 = fmaxf(acc[nb][0] + b1lo, 0.f);   // (rlo, col even)
            float h01 = fmaxf(acc[nb][1] + b1lo, 0.f);   // (rlo, col odd)
            float h10 = fmaxf(acc[nb][2] + b1hi, 0.f);   // (rhi, col even)
            float h11 = fmaxf(acc[nb][3] + b1hi, 0.f);   // (rhi, col odd)
            p[nb * 4 + 0] = fmaf(w2lo0, h00, w2hi0 * h10);
            p[nb * 4 + 1] = fmaf(w2lo1, h00, w2hi1 * h10);
            p[nb * 4 + 2] = fmaf(w2lo0, h01, w2hi0 * h11);
            p[nb * 4 + 3] = fmaf(w2lo1, h01, w2hi1 * h11);
        }
        // reduce over g (8 lanes sharing t4)
#pragma unroll
        for (int j = 0; j < 28; ++j) {
            p[j] += __shfl_down_sync(0xffffffffu, p[j], 16);
            p[j] += __shfl_down_sync(0xffffffffu, p[j], 8);
            p[j] += __shfl_down_sync(0xffffffffu, p[j], 4);
        }
        __syncthreads();                // sred free from prior use
        if (lane < 4) {
#pragma unroll
            for (int j = 0; j < 28; ++j) sred[warp][lane][j] = p[j];
        }
        __syncthreads();

        // z[t][col]: sum 8 warps of the matching n-half
        if (tid < 2 * NTILE) {
            int t   = tid >= NTILE;
            int col = tid - t * NTILE;
            int nh  = col >= 56;
            int ch  = col - nh * 56;
            int nb  = ch >> 3;
            int tt4 = (ch >> 1) & 3;
            int r   = ch & 1;
            int pj  = nb * 4 + r * 2 + t;
            float z = b2[e * 2 + t];
#pragma unroll
            for (int w8 = 0; w8 < 8; ++w8) z += sred[nh * 8 + w8][tt4][pj];
            sz[t][col] = z;
        }
        __syncthreads();

        // 2-way softmax over t, gate-weighted accumulate
        if (tid < NTILE) {
            float z0 = sz[0][tid], z1 = sz[1][tid];
            float mm = fmaxf(z0, z1);
            float a0 = expf(z0 - mm), a1 = expf(z1 - mm);
            float is = 1.f / (a0 + a1);
            ysum[0][tid] += gw * a0 * is;
            ysum[1][tid] += gw * a1 * is;
        }
        __syncthreads();
    }

    if (tid < 2 * NTILE) {
        int t = tid >= NTILE, l = tid - t * NTILE;
        int gl = l0 + l;
        if (gl < LOUT)
            out[((size_t)b * 2 + t) * LOUT + gl] = ysum[t][l];
    }
}

// ---------------- launcher ------------------------------------------------
extern "C" void kernel_launch(void* const* d_in, const int* in_sizes, int n_in,
                              void* d_out, int out_size)
{
    const float* x       = (const float*)d_in[0];
    const float* noise   = (const float*)d_in[1];
    const float* w_gate  = (const float*)d_in[2];
    const float* w_noise = (const float*)d_in[3];
    const float* W1      = (const float*)d_in[4];
    const float* b1      = (const float*)d_in[5];
    const float* W2      = (const float*)d_in[6];
    const float* b2      = (const float*)d_in[7];
    float* out = (float*)d_out;

    k_gatex<<<BQ * CIN / 4, 128>>>(x);
    k_gate<<<1, 32>>>(noise, w_gate, w_noise, out, out_size - 1);
    dim3 grid(NTILES, BQ);
    k_conv<<<grid, 512>>>(x, W1, b1, W2, b2, out);
}